// round 1
// baseline (speedup 1.0000x reference)
#include <cuda_runtime.h>

#define L_FIXED 2048
#define TILE    128
#define NT      (L_FIXED / TILE)          // 16 tiles per side
#define NTP     (NT * (NT + 1) / 2)       // 136 triangle tile-pairs
#define MAXB    16
#define EPSF    1e-8f

// ---- scratch (no allocations allowed) ----
__device__ float g_px[MAXB * L_FIXED];
__device__ float g_py[MAXB * L_FIXED];
__device__ float g_pz[MAXB * L_FIXED];
__device__ float g_stats[MAXB * 8];       // per batch: bn, bd, S, SQ, A1, A2
__device__ float g_partial[MAXB * NTP];

typedef unsigned long long ull;

// ---- Blackwell packed f32x2 helpers ----
__device__ __forceinline__ ull pack2(float x) {
    ull r; asm("mov.b64 %0, {%1, %1};" : "=l"(r) : "f"(x)); return r;
}
__device__ __forceinline__ ull add2(ull a, ull b) {
    ull r; asm("add.rn.f32x2 %0, %1, %2;" : "=l"(r) : "l"(a), "l"(b)); return r;
}
__device__ __forceinline__ ull fma2(ull a, ull b, ull c) {
    ull r; asm("fma.rn.f32x2 %0, %1, %2, %3;" : "=l"(r) : "l"(a), "l"(b), "l"(c)); return r;
}
__device__ __forceinline__ void unpack2(ull v, float &lo, float &hi) {
    asm("mov.b64 {%0, %1}, %2;" : "=f"(lo), "=f"(hi) : "l"(v));
}
__device__ __forceinline__ float sqrt_apx(float x) {
    float r; asm("sqrt.approx.f32 %0, %1;" : "=f"(r) : "f"(x)); return r;
}

// ============================================================
// Kernel 1: per-batch O(L) pass — bond term, mask statistics,
//           displaced position buffers (masked atoms moved far away).
// ============================================================
__global__ void __launch_bounds__(256) prep_kernel(
    const float* __restrict__ pos, const float* __restrict__ mask, int L)
{
    int b   = blockIdx.x;
    int tid = threadIdx.x;
    const float* p = pos  + (size_t)b * L * 3;
    const float* m = mask + (size_t)b * L;

    float bn = 0.f, bd = 0.f, S = 0.f, SQ = 0.f, A1 = 0.f, A2 = 0.f;

    for (int i = tid; i < L; i += 256) {
        float x = p[3*i], y = p[3*i+1], z = p[3*i+2];
        float mi = m[i];
        bool keep = (mi != 0.0f);
        // masked atoms: placed on a sparse far-away line -> never within 1.5 of anything
        g_px[b * L_FIXED + i] = keep ? x : (3.0e7f + 16.0f * (float)i);
        g_py[b * L_FIXED + i] = keep ? y : 0.0f;
        g_pz[b * L_FIXED + i] = keep ? z : 0.0f;

        S  += mi;
        SQ += mi * mi;
        if (i + 1 < L) {
            float mj = m[i+1];
            float dx = p[3*(i+1)]   - x;
            float dy = p[3*(i+1)+1] - y;
            float dz = p[3*(i+1)+2] - z;
            float d  = sqrtf(dx*dx + dy*dy + dz*dz + EPSF);
            float viol = fmaxf(fabsf(d - 3.8f) - 0.4f, 0.0f);
            float mm = mi * mj;
            bn += viol * mm;
            bd += mm;
            A1 += mm;
        }
        if (i + 2 < L) A2 += mi * m[i+2];
    }

    __shared__ float sred[256];
    float vals[6] = {bn, bd, S, SQ, A1, A2};
    #pragma unroll
    for (int v = 0; v < 6; v++) {
        sred[tid] = vals[v];
        __syncthreads();
        for (int off = 128; off > 0; off >>= 1) {
            if (tid < off) sred[tid] += sred[tid + off];
            __syncthreads();
        }
        if (tid == 0) g_stats[b * 8 + v] = sred[0];
        __syncthreads();
    }
}

// ============================================================
// Kernel 2: clash term over upper-triangle 128x128 tiles.
// Each thread owns 2 consecutive i rows; j streamed packed x2 from shared.
// Branchless: v = max(1.5 - sqrt_apx(d2 + eps), 0)  (exact 0 for non-hits).
// ============================================================
__global__ void __launch_bounds__(128) clash_kernel()
{
    int p   = blockIdx.x;     // tile-pair index in [0, NTP)
    int b   = blockIdx.y;
    int tid = threadIdx.x;

    // decode triangular (ti, tj), tj >= ti
    int ti = 0, rem = p;
    while (rem >= NT - ti) { rem -= NT - ti; ti++; }
    int tj = ti + rem;
    int i0 = ti * TILE, j0 = tj * TILE;

    const float* bx = g_px + b * L_FIXED;
    const float* by = g_py + b * L_FIXED;
    const float* bz = g_pz + b * L_FIXED;

    __shared__ ull sx2[TILE/2], sy2[TILE/2], sz2[TILE/2];
    // store NEGATED j positions so dx = xi + (-xj) uses add.f32x2
    ((float*)sx2)[tid] = -bx[j0 + tid];
    ((float*)sy2)[tid] = -by[j0 + tid];
    ((float*)sz2)[tid] = -bz[j0 + tid];
    __syncthreads();

    int il = tid & 63;        // i-pair lane
    int h  = tid >> 6;        // j half (0 or 1)
    int iA = i0 + 2 * il;
    int iB = iA + 1;

    ull xA = pack2(bx[iA]), yA = pack2(by[iA]), zA = pack2(bz[iA]);
    ull xB = pack2(bx[iB]), yB = pack2(by[iB]), zB = pack2(bz[iB]);
    const ull EPS2 = pack2(EPSF);

    float accA = 0.f, accB = 0.f;
    int kbase = h * 32;       // 32 packed-j iterations per thread (64 j's)

    bool need_mask = (tj - ti) <= 1;   // tiles containing |i-j|<=2 pairs

    if (!need_mask) {
        #pragma unroll 8
        for (int k = 0; k < 32; k++) {
            ull njx = sx2[kbase + k];
            ull njy = sy2[kbase + k];
            ull njz = sz2[kbase + k];
            {
                ull dx = add2(xA, njx), dy = add2(yA, njy), dz = add2(zA, njz);
                ull d2 = fma2(dx, dx, EPS2); d2 = fma2(dy, dy, d2); d2 = fma2(dz, dz, d2);
                float lo, hi; unpack2(d2, lo, hi);
                accA += fmaxf(1.5f - sqrt_apx(lo), 0.0f);
                accA += fmaxf(1.5f - sqrt_apx(hi), 0.0f);
            }
            {
                ull dx = add2(xB, njx), dy = add2(yB, njy), dz = add2(zB, njz);
                ull d2 = fma2(dx, dx, EPS2); d2 = fma2(dy, dy, d2); d2 = fma2(dz, dz, d2);
                float lo, hi; unpack2(d2, lo, hi);
                accB += fmaxf(1.5f - sqrt_apx(lo), 0.0f);
                accB += fmaxf(1.5f - sqrt_apx(hi), 0.0f);
            }
        }
    } else {
        #pragma unroll 4
        for (int k = 0; k < 32; k++) {
            ull njx = sx2[kbase + k];
            ull njy = sy2[kbase + k];
            ull njz = sz2[kbase + k];
            int jlo = j0 + 2 * (kbase + k);
            int jhi = jlo + 1;
            {
                ull dx = add2(xA, njx), dy = add2(yA, njy), dz = add2(zA, njz);
                ull d2 = fma2(dx, dx, EPS2); d2 = fma2(dy, dy, d2); d2 = fma2(dz, dz, d2);
                float lo, hi; unpack2(d2, lo, hi);
                float vl = fmaxf(1.5f - sqrt_apx(lo), 0.0f);
                float vh = fmaxf(1.5f - sqrt_apx(hi), 0.0f);
                if (jlo - iA <= 2) vl = 0.0f;
                if (jhi - iA <= 2) vh = 0.0f;
                accA += vl + vh;
            }
            {
                ull dx = add2(xB, njx), dy = add2(yB, njy), dz = add2(zB, njz);
                ull d2 = fma2(dx, dx, EPS2); d2 = fma2(dy, dy, d2); d2 = fma2(dz, dz, d2);
                float lo, hi; unpack2(d2, lo, hi);
                float vl = fmaxf(1.5f - sqrt_apx(lo), 0.0f);
                float vh = fmaxf(1.5f - sqrt_apx(hi), 0.0f);
                if (jlo - iB <= 2) vl = 0.0f;
                if (jhi - iB <= 2) vh = 0.0f;
                accB += vl + vh;
            }
        }
    }

    __shared__ float sred[128];
    sred[tid] = accA + accB;
    __syncthreads();
    for (int off = 64; off > 0; off >>= 1) {
        if (tid < off) sred[tid] += sred[tid + off];
        __syncthreads();
    }
    if (tid == 0) g_partial[b * NTP + p] = sred[0];
}

// ============================================================
// Kernel 3: deterministic final reduction + loss assembly.
// ============================================================
__global__ void __launch_bounds__(256) final_kernel(float* out, int B, int nPart)
{
    __shared__ double sred[256];
    int tid = threadIdx.x;
    double s = 0.0;
    for (int i = tid; i < nPart; i += 256) s += (double)g_partial[i];
    sred[tid] = s;
    __syncthreads();
    for (int off = 128; off > 0; off >>= 1) {
        if (tid < off) sred[tid] += sred[tid + off];
        __syncthreads();
    }
    if (tid == 0) {
        double clash_num = 2.0 * sred[0];     // upper triangle counted once -> double
        double bn = 0.0, bd = 0.0, pd = 0.0;
        for (int b = 0; b < B; b++) {
            bn += (double)g_stats[b * 8 + 0];
            bd += (double)g_stats[b * 8 + 1];
            double S  = (double)g_stats[b * 8 + 2];
            double SQ = (double)g_stats[b * 8 + 3];
            double A1 = (double)g_stats[b * 8 + 4];
            double A2 = (double)g_stats[b * 8 + 5];
            pd += S * S - SQ - 2.0 * A1 - 2.0 * A2;   // sum of non-bonded pair mask
        }
        double bond  = bn / (bd + 1e-8);
        double clash = clash_num / (pd + 1e-8);
        out[0] = (float)bond;
        out[1] = (float)clash;
        out[2] = (float)(bond + clash);
    }
}

extern "C" void kernel_launch(void* const* d_in, const int* in_sizes, int n_in,
                              void* d_out, int out_size)
{
    const float* pos  = (const float*)d_in[0];
    const float* mask = (const float*)d_in[1];
    int L = L_FIXED;
    int B = in_sizes[1] / L;
    if (B > MAXB) B = MAXB;

    prep_kernel<<<B, 256>>>(pos, mask, L);
    dim3 grid(NTP, B);
    clash_kernel<<<grid, 128>>>();
    final_kernel<<<1, 256>>>((float*)d_out, B, B * NTP);
}

// round 2
// speedup vs baseline: 1.5342x; 1.5342x over previous
#include <cuda_runtime.h>

#define L_FIXED 2048
#define TILE    128
#define NT      (L_FIXED / TILE)          // 16
#define NTP     (NT * (NT + 1) / 2)       // 136
#define MAXB    16
#define EPSF    1e-8f
#define CLASH2  2.25f                     // 1.5^2

typedef unsigned long long ull;

// ---- global accumulators (zero-initialized at load, reset by finalize) ----
__device__ double   g_clash = 0.0;
__device__ double   g_bn    = 0.0;
__device__ double   g_bd    = 0.0;
__device__ double   g_lin   = 0.0;        // sum over batches of SQ + 2*A1 + 2*A2
__device__ double   g_S[MAXB];            // per-batch mask sum (needed squared)
__device__ unsigned g_count = 0;

// ---- Blackwell packed f32x2 helpers ----
__device__ __forceinline__ ull pack2(float x) {
    ull r; asm("mov.b64 %0, {%1, %1};" : "=l"(r) : "f"(x)); return r;
}
__device__ __forceinline__ ull add2(ull a, ull b) {
    ull r; asm("add.rn.f32x2 %0, %1, %2;" : "=l"(r) : "l"(a), "l"(b)); return r;
}
__device__ __forceinline__ ull mul2(ull a, ull b) {
    ull r; asm("mul.rn.f32x2 %0, %1, %2;" : "=l"(r) : "l"(a), "l"(b)); return r;
}
__device__ __forceinline__ ull fma2(ull a, ull b, ull c) {
    ull r; asm("fma.rn.f32x2 %0, %1, %2, %3;" : "=l"(r) : "l"(a), "l"(b), "l"(c)); return r;
}
__device__ __forceinline__ void unpack2(ull v, float &lo, float &hi) {
    asm("mov.b64 {%0, %1}, %2;" : "=f"(lo), "=f"(hi) : "l"(v));
}
__device__ __forceinline__ float sqrt_apx(float x) {
    float r; asm("sqrt.approx.f32 %0, %1;" : "=f"(r) : "f"(x)); return r;
}
__device__ __forceinline__ float warp_sum(float v) {
    #pragma unroll
    for (int off = 16; off > 0; off >>= 1)
        v += __shfl_down_sync(0xffffffffu, v, off);
    return v;
}

// ============================================================
// Single fused kernel. grid = (NTP, B), block = 128.
//  - every block: one 128x128 upper-triangle clash tile (4 i-rows/thread)
//  - diagonal blocks: also bond term + mask statistics for their i-range
//  - last finishing block: assembles losses, writes out, resets accumulators
// ============================================================
__global__ void __launch_bounds__(128)
fused_violation_kernel(const float* __restrict__ pos,
                       const float* __restrict__ mask,
                       float* __restrict__ out, int B)
{
    const int p   = blockIdx.x;
    const int b   = blockIdx.y;
    const int tid = threadIdx.x;

    // decode triangular (ti, tj), tj >= ti
    int ti = 0, rem = p;
    while (rem >= NT - ti) { rem -= NT - ti; ti++; }
    const int tj = ti + rem;
    const int i0 = ti * TILE, j0 = tj * TILE;

    const float* P = pos  + (size_t)b * L_FIXED * 3;
    const float* M = mask + (size_t)b * L_FIXED;

    // ---- stage j tile into shared (negated, displacement for masked atoms) ----
    __shared__ ull sjx[TILE / 2], sjy[TILE / 2], sjz[TILE / 2];
    {
        int j = j0 + tid;
        float mj = M[j];
        bool keep = (mj != 0.0f);
        float x = P[3 * j], y = P[3 * j + 1], z = P[3 * j + 2];
        ((float*)sjx)[tid] = keep ? -x : -(3.0e7f + 16.0f * (float)j);
        ((float*)sjy)[tid] = keep ? -y : 0.0f;
        ((float*)sjz)[tid] = keep ? -z : 0.0f;
    }

    // ---- per-thread i rows (4 consecutive), displaced + broadcast-packed ----
    const int q = tid & 31;          // i quad index
    const int s = tid >> 5;          // j quarter (16 packed j's each)
    const int ibase = i0 + 4 * q;
    ull xr[4], yr[4], zr[4];
    #pragma unroll
    for (int r = 0; r < 4; r++) {
        int i = ibase + r;
        float mi = M[i];
        bool keep = (mi != 0.0f);
        float x = P[3 * i], y = P[3 * i + 1], z = P[3 * i + 2];
        xr[r] = pack2(keep ? x : (3.0e7f + 16.0f * (float)i));
        yr[r] = pack2(keep ? y : 0.0f);
        zr[r] = pack2(keep ? z : 0.0f);
    }
    __syncthreads();

    float acc = 0.0f;
    const int k0 = s * 16;

    if (tj - ti >= 2) {
        // far tiles: no seq-sep mask possible; d2-only fast path, rare sqrt
        #pragma unroll 4
        for (int k = k0; k < k0 + 16; k++) {
            ull nx = sjx[k], ny = sjy[k], nz = sjz[k];
            float lo[4], hi[4];
            float mn0, mn1;
            {
                ull dx = add2(xr[0], nx), dy = add2(yr[0], ny), dz = add2(zr[0], nz);
                ull d2 = fma2(dz, dz, fma2(dy, dy, mul2(dx, dx)));
                unpack2(d2, lo[0], hi[0]);
            }
            {
                ull dx = add2(xr[1], nx), dy = add2(yr[1], ny), dz = add2(zr[1], nz);
                ull d2 = fma2(dz, dz, fma2(dy, dy, mul2(dx, dx)));
                unpack2(d2, lo[1], hi[1]);
            }
            mn0 = fminf(fminf(lo[0], hi[0]), fminf(lo[1], hi[1]));
            {
                ull dx = add2(xr[2], nx), dy = add2(yr[2], ny), dz = add2(zr[2], nz);
                ull d2 = fma2(dz, dz, fma2(dy, dy, mul2(dx, dx)));
                unpack2(d2, lo[2], hi[2]);
            }
            {
                ull dx = add2(xr[3], nx), dy = add2(yr[3], ny), dz = add2(zr[3], nz);
                ull d2 = fma2(dz, dz, fma2(dy, dy, mul2(dx, dx)));
                unpack2(d2, lo[3], hi[3]);
            }
            mn1 = fminf(fminf(lo[2], hi[2]), fminf(lo[3], hi[3]));
            if (fminf(mn0, mn1) < CLASH2) {
                #pragma unroll
                for (int r = 0; r < 4; r++) {
                    acc += fmaxf(1.5f - sqrtf(lo[r] + EPSF), 0.0f);
                    acc += fmaxf(1.5f - sqrtf(hi[r] + EPSF), 0.0f);
                }
            }
        }
    } else {
        // near-diagonal tiles: seq-sep mask needed; branchless approx-sqrt path
        const ull EPS2 = pack2(EPSF);
        #pragma unroll 2
        for (int k = k0; k < k0 + 16; k++) {
            ull nx = sjx[k], ny = sjy[k], nz = sjz[k];
            int jlo = j0 + 2 * k, jhi = jlo + 1;
            #pragma unroll
            for (int r = 0; r < 4; r++) {
                int i = ibase + r;
                ull dx = add2(xr[r], nx), dy = add2(yr[r], ny), dz = add2(zr[r], nz);
                ull d2 = fma2(dz, dz, fma2(dy, dy, fma2(dx, dx, EPS2)));
                float lo, hi; unpack2(d2, lo, hi);
                float vl = fmaxf(1.5f - sqrt_apx(lo), 0.0f);
                float vh = fmaxf(1.5f - sqrt_apx(hi), 0.0f);
                if (jlo - i <= 2) vl = 0.0f;   // masks j<=i and |i-j|<=2
                if (jhi - i <= 2) vh = 0.0f;
                acc += vl + vh;
            }
        }
    }

    // ---- block reduction of clash partial ----
    __shared__ float swr[4];
    acc = warp_sum(acc);
    if ((tid & 31) == 0) swr[tid >> 5] = acc;
    __syncthreads();
    if (tid == 0)
        atomicAdd(&g_clash, (double)(swr[0] + swr[1] + swr[2] + swr[3]));

    // ---- diagonal blocks: bond term + mask statistics for rows [i0, i0+128) ----
    if (ti == tj) {
        int i = i0 + tid;
        float mi = M[i];
        float S = mi, lin = mi * mi;
        float bn = 0.0f, bd = 0.0f;
        if (i + 1 < L_FIXED) {
            float mj = M[i + 1];
            float dx = P[3 * (i + 1)]     - P[3 * i];
            float dy = P[3 * (i + 1) + 1] - P[3 * i + 1];
            float dz = P[3 * (i + 1) + 2] - P[3 * i + 2];
            float d  = sqrtf(dx * dx + dy * dy + dz * dz + EPSF);
            float viol = fmaxf(fabsf(d - 3.8f) - 0.4f, 0.0f);
            bd = mi * mj;
            bn = viol * bd;
            lin += 2.0f * bd;                 // 2*A1
        }
        if (i + 2 < L_FIXED) lin += 2.0f * mi * M[i + 2];   // 2*A2

        bn  = warp_sum(bn);
        bd  = warp_sum(bd);
        S   = warp_sum(S);
        lin = warp_sum(lin);
        __shared__ float sst[4][4];
        if ((tid & 31) == 0) {
            int w = tid >> 5;
            sst[w][0] = bn; sst[w][1] = bd; sst[w][2] = S; sst[w][3] = lin;
        }
        __syncthreads();
        if (tid == 0) {
            double tbn = 0, tbd = 0, tS = 0, tlin = 0;
            #pragma unroll
            for (int w = 0; w < 4; w++) {
                tbn += sst[w][0]; tbd += sst[w][1];
                tS  += sst[w][2]; tlin += sst[w][3];
            }
            atomicAdd(&g_bn,  tbn);
            atomicAdd(&g_bd,  tbd);
            atomicAdd(&g_S[b], tS);
            atomicAdd(&g_lin, tlin);
        }
    }

    // ---- last-block finalize ----
    __threadfence();
    __shared__ bool is_last;
    if (tid == 0) {
        unsigned total = gridDim.x * gridDim.y;
        is_last = (atomicAdd(&g_count, 1u) == total - 1u);
    }
    __syncthreads();
    if (is_last && tid == 0) {
        double pd = 0.0;
        #pragma unroll
        for (int bb = 0; bb < MAXB; bb++) {
            if (bb < B) {
                double Sb = *((volatile double*)&g_S[bb]);
                pd += Sb * Sb;
            }
        }
        pd -= *((volatile double*)&g_lin);
        double bn = *((volatile double*)&g_bn);
        double bd = *((volatile double*)&g_bd);
        double cl = *((volatile double*)&g_clash);
        double bond  = bn / (bd + 1e-8);
        double clash = 2.0 * cl / (pd + 1e-8);
        out[0] = (float)bond;
        out[1] = (float)clash;
        out[2] = (float)(bond + clash);
        // reset for next graph replay
        g_clash = 0.0; g_bn = 0.0; g_bd = 0.0; g_lin = 0.0; g_count = 0u;
        #pragma unroll
        for (int bb = 0; bb < MAXB; bb++) g_S[bb] = 0.0;
    }
}

extern "C" void kernel_launch(void* const* d_in, const int* in_sizes, int n_in,
                              void* d_out, int out_size)
{
    const float* pos  = (const float*)d_in[0];
    const float* mask = (const float*)d_in[1];
    int B = in_sizes[1] / L_FIXED;
    if (B > MAXB) B = MAXB;

    dim3 grid(NTP, B);
    fused_violation_kernel<<<grid, 128>>>(pos, mask, (float*)d_out, B);
}

// round 3
// speedup vs baseline: 1.5524x; 1.0118x over previous
#include <cuda_runtime.h>

#define L_FIXED 2048
#define TILE    128
#define NT      (L_FIXED / TILE)          // 16
#define NTP     (NT * (NT + 1) / 2)       // 136
#define MAXB    16
#define EPSF    1e-8f
#define CLASH2  2.25f                     // 1.5^2
#define NTHREADS 256

typedef unsigned long long ull;

// ---- global accumulators (zero-initialized at load, reset by finalize) ----
__device__ double   g_clash = 0.0;
__device__ double   g_bn    = 0.0;
__device__ double   g_bd    = 0.0;
__device__ double   g_lin   = 0.0;        // sum over batches of SQ + 2*A1 + 2*A2
__device__ double   g_S[MAXB];            // per-batch mask sum (needed squared)
__device__ unsigned g_count = 0;

// ---- Blackwell packed f32x2 helpers ----
__device__ __forceinline__ ull pack2(float x) {
    ull r; asm("mov.b64 %0, {%1, %1};" : "=l"(r) : "f"(x)); return r;
}
__device__ __forceinline__ ull add2(ull a, ull b) {
    ull r; asm("add.rn.f32x2 %0, %1, %2;" : "=l"(r) : "l"(a), "l"(b)); return r;
}
__device__ __forceinline__ ull mul2(ull a, ull b) {
    ull r; asm("mul.rn.f32x2 %0, %1, %2;" : "=l"(r) : "l"(a), "l"(b)); return r;
}
__device__ __forceinline__ ull fma2(ull a, ull b, ull c) {
    ull r; asm("fma.rn.f32x2 %0, %1, %2, %3;" : "=l"(r) : "l"(a), "l"(b), "l"(c)); return r;
}
__device__ __forceinline__ void unpack2(ull v, float &lo, float &hi) {
    asm("mov.b64 {%0, %1}, %2;" : "=f"(lo), "=f"(hi) : "l"(v));
}
__device__ __forceinline__ float sqrt_apx(float x) {
    float r; asm("sqrt.approx.f32 %0, %1;" : "=f"(r) : "f"(x)); return r;
}
__device__ __forceinline__ float warp_sum(float v) {
    #pragma unroll
    for (int off = 16; off > 0; off >>= 1)
        v += __shfl_down_sync(0xffffffffu, v, off);
    return v;
}

// ============================================================
// Single fused kernel. grid = (NTP, B), block = 256.
//  - every block: one 128x128 upper-triangle clash tile (4 i-rows/thread,
//    each thread covers a 1/8 slice of packed j)
//  - diagonal blocks: also bond term + mask statistics for their i-range
//  - last finishing block: assembles losses, writes out, resets accumulators
// ============================================================
__global__ void __launch_bounds__(NTHREADS)
fused_violation_kernel(const float* __restrict__ pos,
                       const float* __restrict__ mask,
                       float* __restrict__ out, int B)
{
    const int p   = blockIdx.x;
    const int b   = blockIdx.y;
    const int tid = threadIdx.x;

    // decode triangular (ti, tj), tj >= ti
    int ti = 0, rem = p;
    while (rem >= NT - ti) { rem -= NT - ti; ti++; }
    const int tj = ti + rem;
    const int i0 = ti * TILE, j0 = tj * TILE;

    const float* P = pos  + (size_t)b * L_FIXED * 3;
    const float* M = mask + (size_t)b * L_FIXED;

    // ---- stage j tile into shared (negated, displacement for masked atoms) ----
    __shared__ ull sjx[TILE / 2], sjy[TILE / 2], sjz[TILE / 2];
    if (tid < TILE) {
        int j = j0 + tid;
        float mj = M[j];
        bool keep = (mj != 0.0f);
        float x = P[3 * j], y = P[3 * j + 1], z = P[3 * j + 2];
        ((float*)sjx)[tid] = keep ? -x : -(3.0e7f + 16.0f * (float)j);
        ((float*)sjy)[tid] = keep ? -y : 0.0f;
        ((float*)sjz)[tid] = keep ? -z : 0.0f;
    }

    // ---- per-thread i rows (4 consecutive) via 3x LDG.128, displaced+packed ----
    const int q = tid & 31;          // i quad index (32 quads cover 128 rows)
    const int s = tid >> 5;          // j eighth (8 packed j's each)
    const int ibase = i0 + 4 * q;
    ull xr[4], yr[4], zr[4];
    {
        const float4* P4 = (const float4*)(P + 3 * ibase);
        float4 v0 = P4[0], v1 = P4[1], v2 = P4[2];
        float c[12] = {v0.x, v0.y, v0.z, v0.w, v1.x, v1.y, v1.z, v1.w,
                       v2.x, v2.y, v2.z, v2.w};
        #pragma unroll
        for (int r = 0; r < 4; r++) {
            int i = ibase + r;
            bool keep = (M[i] != 0.0f);
            xr[r] = pack2(keep ? c[3 * r]     : (3.0e7f + 16.0f * (float)i));
            yr[r] = pack2(keep ? c[3 * r + 1] : 0.0f);
            zr[r] = pack2(keep ? c[3 * r + 2] : 0.0f);
        }
    }
    __syncthreads();

    float acc = 0.0f;
    const int k0 = s * 8;

    if (tj - ti >= 2) {
        // far tiles: d2-only fast path, rare sqrt
        #pragma unroll
        for (int k = k0; k < k0 + 8; k++) {
            ull nx = sjx[k], ny = sjy[k], nz = sjz[k];
            float lo[4], hi[4];
            {
                ull dx = add2(xr[0], nx), dy = add2(yr[0], ny), dz = add2(zr[0], nz);
                ull d2 = fma2(dz, dz, fma2(dy, dy, mul2(dx, dx)));
                unpack2(d2, lo[0], hi[0]);
            }
            {
                ull dx = add2(xr[1], nx), dy = add2(yr[1], ny), dz = add2(zr[1], nz);
                ull d2 = fma2(dz, dz, fma2(dy, dy, mul2(dx, dx)));
                unpack2(d2, lo[1], hi[1]);
            }
            float mn0 = fminf(fminf(lo[0], hi[0]), fminf(lo[1], hi[1]));
            {
                ull dx = add2(xr[2], nx), dy = add2(yr[2], ny), dz = add2(zr[2], nz);
                ull d2 = fma2(dz, dz, fma2(dy, dy, mul2(dx, dx)));
                unpack2(d2, lo[2], hi[2]);
            }
            {
                ull dx = add2(xr[3], nx), dy = add2(yr[3], ny), dz = add2(zr[3], nz);
                ull d2 = fma2(dz, dz, fma2(dy, dy, mul2(dx, dx)));
                unpack2(d2, lo[3], hi[3]);
            }
            float mn1 = fminf(fminf(lo[2], hi[2]), fminf(lo[3], hi[3]));
            if (fminf(mn0, mn1) < CLASH2) {
                #pragma unroll
                for (int r = 0; r < 4; r++) {
                    acc += fmaxf(1.5f - sqrtf(lo[r] + EPSF), 0.0f);
                    acc += fmaxf(1.5f - sqrtf(hi[r] + EPSF), 0.0f);
                }
            }
        }
    } else {
        // near-diagonal tiles: seq-sep mask needed; branchless approx-sqrt path
        const ull EPS2 = pack2(EPSF);
        #pragma unroll
        for (int k = k0; k < k0 + 8; k++) {
            ull nx = sjx[k], ny = sjy[k], nz = sjz[k];
            int jlo = j0 + 2 * k, jhi = jlo + 1;
            #pragma unroll
            for (int r = 0; r < 4; r++) {
                int i = ibase + r;
                ull dx = add2(xr[r], nx), dy = add2(yr[r], ny), dz = add2(zr[r], nz);
                ull d2 = fma2(dz, dz, fma2(dy, dy, fma2(dx, dx, EPS2)));
                float lo, hi; unpack2(d2, lo, hi);
                float vl = fmaxf(1.5f - sqrt_apx(lo), 0.0f);
                float vh = fmaxf(1.5f - sqrt_apx(hi), 0.0f);
                if (jlo - i <= 2) vl = 0.0f;   // masks j<=i and |i-j|<=2
                if (jhi - i <= 2) vh = 0.0f;
                acc += vl + vh;
            }
        }
    }

    // ---- block reduction of clash partial ----
    __shared__ float swr[NTHREADS / 32];
    acc = warp_sum(acc);
    if ((tid & 31) == 0) swr[tid >> 5] = acc;
    __syncthreads();
    if (tid == 0) {
        float t = 0.0f;
        #pragma unroll
        for (int w = 0; w < NTHREADS / 32; w++) t += swr[w];
        atomicAdd(&g_clash, (double)t);
    }

    // ---- diagonal blocks: bond term + mask statistics for rows [i0, i0+128) ----
    if (ti == tj) {
        float bn = 0.0f, bd = 0.0f, S = 0.0f, lin = 0.0f;
        if (tid < TILE) {
            int i = i0 + tid;
            float mi = M[i];
            S = mi; lin = mi * mi;
            if (i + 1 < L_FIXED) {
                float mj = M[i + 1];
                float dx = P[3 * (i + 1)]     - P[3 * i];
                float dy = P[3 * (i + 1) + 1] - P[3 * i + 1];
                float dz = P[3 * (i + 1) + 2] - P[3 * i + 2];
                float d  = sqrtf(dx * dx + dy * dy + dz * dz + EPSF);
                float viol = fmaxf(fabsf(d - 3.8f) - 0.4f, 0.0f);
                bd = mi * mj;
                bn = viol * bd;
                lin += 2.0f * bd;                              // 2*A1
            }
            if (i + 2 < L_FIXED) lin += 2.0f * mi * M[i + 2];  // 2*A2
        }
        bn  = warp_sum(bn);
        bd  = warp_sum(bd);
        S   = warp_sum(S);
        lin = warp_sum(lin);
        __shared__ float sst[NTHREADS / 32][4];
        if ((tid & 31) == 0) {
            int w = tid >> 5;
            sst[w][0] = bn; sst[w][1] = bd; sst[w][2] = S; sst[w][3] = lin;
        }
        __syncthreads();
        if (tid == 0) {
            double tbn = 0, tbd = 0, tS = 0, tlin = 0;
            #pragma unroll
            for (int w = 0; w < NTHREADS / 32; w++) {
                tbn += sst[w][0]; tbd += sst[w][1];
                tS  += sst[w][2]; tlin += sst[w][3];
            }
            atomicAdd(&g_bn,  tbn);
            atomicAdd(&g_bd,  tbd);
            atomicAdd(&g_S[b], tS);
            atomicAdd(&g_lin, tlin);
        }
    }

    // ---- last-block finalize ----
    __threadfence();
    __shared__ bool is_last;
    if (tid == 0) {
        unsigned total = gridDim.x * gridDim.y;
        is_last = (atomicAdd(&g_count, 1u) == total - 1u);
    }
    __syncthreads();
    if (is_last && tid == 0) {
        double pd = 0.0;
        #pragma unroll
        for (int bb = 0; bb < MAXB; bb++) {
            if (bb < B) {
                double Sb = *((volatile double*)&g_S[bb]);
                pd += Sb * Sb;
            }
        }
        pd -= *((volatile double*)&g_lin);
        double bn = *((volatile double*)&g_bn);
        double bd = *((volatile double*)&g_bd);
        double cl = *((volatile double*)&g_clash);
        double bond  = bn / (bd + 1e-8);
        double clash = 2.0 * cl / (pd + 1e-8);
        out[0] = (float)bond;
        out[1] = (float)clash;
        out[2] = (float)(bond + clash);
        // reset for next graph replay
        g_clash = 0.0; g_bn = 0.0; g_bd = 0.0; g_lin = 0.0; g_count = 0u;
        #pragma unroll
        for (int bb = 0; bb < MAXB; bb++) g_S[bb] = 0.0;
    }
}

extern "C" void kernel_launch(void* const* d_in, const int* in_sizes, int n_in,
                              void* d_out, int out_size)
{
    const float* pos  = (const float*)d_in[0];
    const float* mask = (const float*)d_in[1];
    int B = in_sizes[1] / L_FIXED;
    if (B > MAXB) B = MAXB;

    dim3 grid(NTP, B);
    fused_violation_kernel<<<grid, NTHREADS>>>(pos, mask, (float*)d_out, B);
}

// round 4
// speedup vs baseline: 1.5550x; 1.0017x over previous
#include <cuda_runtime.h>

#define L_FIXED 2048
#define TILE    128
#define NT      (L_FIXED / TILE)          // 16
#define NTP     (NT * (NT + 1) / 2)       // 136
#define MAXB    16
#define EPSF    1e-8f
#define CLASH2  2.25f                     // 1.5^2
#define NTHREADS 256

typedef unsigned long long ull;

// ---- global accumulators (zero-initialized at load, reset by finalize) ----
__device__ double   g_clash = 0.0;
__device__ double   g_bn    = 0.0;
__device__ double   g_bd    = 0.0;
__device__ double   g_lin   = 0.0;        // sum over batches of SQ + 2*A1 + 2*A2
__device__ double   g_S[MAXB];            // per-batch mask sum (needed squared)
__device__ unsigned g_count = 0;

// ---- Blackwell packed f32x2 helpers ----
__device__ __forceinline__ ull pack2(float x) {
    ull r; asm("mov.b64 %0, {%1, %1};" : "=l"(r) : "f"(x)); return r;
}
__device__ __forceinline__ ull add2(ull a, ull b) {
    ull r; asm("add.rn.f32x2 %0, %1, %2;" : "=l"(r) : "l"(a), "l"(b)); return r;
}
__device__ __forceinline__ ull mul2(ull a, ull b) {
    ull r; asm("mul.rn.f32x2 %0, %1, %2;" : "=l"(r) : "l"(a), "l"(b)); return r;
}
__device__ __forceinline__ ull fma2(ull a, ull b, ull c) {
    ull r; asm("fma.rn.f32x2 %0, %1, %2, %3;" : "=l"(r) : "l"(a), "l"(b), "l"(c)); return r;
}
__device__ __forceinline__ void unpack2(ull v, float &lo, float &hi) {
    asm("mov.b64 {%0, %1}, %2;" : "=f"(lo), "=f"(hi) : "l"(v));
}
__device__ __forceinline__ float sqrt_apx(float x) {
    float r; asm("sqrt.approx.f32 %0, %1;" : "=f"(r) : "f"(x)); return r;
}
__device__ __forceinline__ float warp_sum(float v) {
    #pragma unroll
    for (int off = 16; off > 0; off >>= 1)
        v += __shfl_down_sync(0xffffffffu, v, off);
    return v;
}

// ============================================================
// Single fused kernel. grid = (NTP, B), block = 256.
//  - every block: one 128x128 upper-triangle clash tile (4 i-rows/thread,
//    each thread covers a 1/8 slice of packed j)
//  - far tiles: d2-only fast path; warp-uniform VOTE gates the rare sqrt path
//  - diagonal blocks: also bond term + mask statistics for their i-range
//  - last finishing block: assembles losses, writes out, resets accumulators
// ============================================================
__global__ void __launch_bounds__(NTHREADS)
fused_violation_kernel(const float* __restrict__ pos,
                       const float* __restrict__ mask,
                       float* __restrict__ out, int B)
{
    const int p   = blockIdx.x;
    const int b   = blockIdx.y;
    const int tid = threadIdx.x;

    // decode triangular (ti, tj), tj >= ti
    int ti = 0, rem = p;
    while (rem >= NT - ti) { rem -= NT - ti; ti++; }
    const int tj = ti + rem;
    const int i0 = ti * TILE, j0 = tj * TILE;

    const float* P = pos  + (size_t)b * L_FIXED * 3;
    const float* M = mask + (size_t)b * L_FIXED;

    // ---- stage j tile into shared (negated, displacement for masked atoms) ----
    __shared__ ull sjx[TILE / 2], sjy[TILE / 2], sjz[TILE / 2];
    if (tid < TILE) {
        int j = j0 + tid;
        float mj = M[j];
        bool keep = (mj != 0.0f);
        float x = P[3 * j], y = P[3 * j + 1], z = P[3 * j + 2];
        ((float*)sjx)[tid] = keep ? -x : -(3.0e7f + 16.0f * (float)j);
        ((float*)sjy)[tid] = keep ? -y : 0.0f;
        ((float*)sjz)[tid] = keep ? -z : 0.0f;
    }

    // ---- per-thread i rows (4 consecutive) via 3x LDG.128, displaced+packed ----
    const int q = tid & 31;          // i quad index (32 quads cover 128 rows)
    const int s = tid >> 5;          // j eighth (8 packed j's each)
    const int ibase = i0 + 4 * q;
    ull xr[4], yr[4], zr[4];
    {
        const float4* P4 = (const float4*)(P + 3 * ibase);
        float4 v0 = P4[0], v1 = P4[1], v2 = P4[2];
        float c[12] = {v0.x, v0.y, v0.z, v0.w, v1.x, v1.y, v1.z, v1.w,
                       v2.x, v2.y, v2.z, v2.w};
        #pragma unroll
        for (int r = 0; r < 4; r++) {
            int i = ibase + r;
            bool keep = (M[i] != 0.0f);
            xr[r] = pack2(keep ? c[3 * r]     : (3.0e7f + 16.0f * (float)i));
            yr[r] = pack2(keep ? c[3 * r + 1] : 0.0f);
            zr[r] = pack2(keep ? c[3 * r + 2] : 0.0f);
        }
    }
    __syncthreads();

    float acc = 0.0f;
    const int k0 = s * 8;

    if (tj - ti >= 2) {
        // far tiles: d2-only fast path; rare sqrt gated by warp-uniform vote
        #pragma unroll
        for (int k = k0; k < k0 + 8; k++) {
            ull nx = sjx[k], ny = sjy[k], nz = sjz[k];
            float lo[4], hi[4];
            #pragma unroll
            for (int r = 0; r < 4; r++) {
                ull dx = add2(xr[r], nx), dy = add2(yr[r], ny), dz = add2(zr[r], nz);
                ull d2 = fma2(dz, dz, fma2(dy, dy, mul2(dx, dx)));
                unpack2(d2, lo[r], hi[r]);
            }
            float mn = fminf(fminf(fminf(lo[0], hi[0]), fminf(lo[1], hi[1])),
                             fminf(fminf(lo[2], hi[2]), fminf(lo[3], hi[3])));
            // warp-uniform branch: whole warp enters together (~7% of iters)
            if (__any_sync(0xffffffffu, mn < CLASH2)) {
                #pragma unroll
                for (int r = 0; r < 4; r++) {
                    acc += fmaxf(1.5f - sqrt_apx(lo[r] + EPSF), 0.0f);
                    acc += fmaxf(1.5f - sqrt_apx(hi[r] + EPSF), 0.0f);
                }
            }
        }
    } else {
        // near-diagonal tiles: seq-sep mask needed; branchless approx-sqrt path
        const ull EPS2 = pack2(EPSF);
        #pragma unroll
        for (int k = k0; k < k0 + 8; k++) {
            ull nx = sjx[k], ny = sjy[k], nz = sjz[k];
            int jlo = j0 + 2 * k, jhi = jlo + 1;
            #pragma unroll
            for (int r = 0; r < 4; r++) {
                int i = ibase + r;
                ull dx = add2(xr[r], nx), dy = add2(yr[r], ny), dz = add2(zr[r], nz);
                ull d2 = fma2(dz, dz, fma2(dy, dy, fma2(dx, dx, EPS2)));
                float lo, hi; unpack2(d2, lo, hi);
                float vl = fmaxf(1.5f - sqrt_apx(lo), 0.0f);
                float vh = fmaxf(1.5f - sqrt_apx(hi), 0.0f);
                if (jlo - i <= 2) vl = 0.0f;   // masks j<=i and |i-j|<=2
                if (jhi - i <= 2) vh = 0.0f;
                acc += vl + vh;
            }
        }
    }

    // ---- block reduction of clash partial ----
    __shared__ float swr[NTHREADS / 32];
    acc = warp_sum(acc);
    if ((tid & 31) == 0) swr[tid >> 5] = acc;
    __syncthreads();
    if (tid == 0) {
        float t = 0.0f;
        #pragma unroll
        for (int w = 0; w < NTHREADS / 32; w++) t += swr[w];
        atomicAdd(&g_clash, (double)t);
    }

    // ---- diagonal blocks: bond term + mask statistics for rows [i0, i0+128) ----
    if (ti == tj) {
        float bn = 0.0f, bd = 0.0f, S = 0.0f, lin = 0.0f;
        if (tid < TILE) {
            int i = i0 + tid;
            float mi = M[i];
            S = mi; lin = mi * mi;
            if (i + 1 < L_FIXED) {
                float mj = M[i + 1];
                float dx = P[3 * (i + 1)]     - P[3 * i];
                float dy = P[3 * (i + 1) + 1] - P[3 * i + 1];
                float dz = P[3 * (i + 1) + 2] - P[3 * i + 2];
                float d  = sqrtf(dx * dx + dy * dy + dz * dz + EPSF);
                float viol = fmaxf(fabsf(d - 3.8f) - 0.4f, 0.0f);
                bd = mi * mj;
                bn = viol * bd;
                lin += 2.0f * bd;                              // 2*A1
            }
            if (i + 2 < L_FIXED) lin += 2.0f * mi * M[i + 2];  // 2*A2
        }
        bn  = warp_sum(bn);
        bd  = warp_sum(bd);
        S   = warp_sum(S);
        lin = warp_sum(lin);
        __shared__ float sst[NTHREADS / 32][4];
        if ((tid & 31) == 0) {
            int w = tid >> 5;
            sst[w][0] = bn; sst[w][1] = bd; sst[w][2] = S; sst[w][3] = lin;
        }
        __syncthreads();
        if (tid == 0) {
            double tbn = 0, tbd = 0, tS = 0, tlin = 0;
            #pragma unroll
            for (int w = 0; w < NTHREADS / 32; w++) {
                tbn += sst[w][0]; tbd += sst[w][1];
                tS  += sst[w][2]; tlin += sst[w][3];
            }
            atomicAdd(&g_bn,  tbn);
            atomicAdd(&g_bd,  tbd);
            atomicAdd(&g_S[b], tS);
            atomicAdd(&g_lin, tlin);
        }
    }

    // ---- last-block finalize ----
    __threadfence();
    __shared__ bool is_last;
    if (tid == 0) {
        unsigned total = gridDim.x * gridDim.y;
        is_last = (atomicAdd(&g_count, 1u) == total - 1u);
    }
    __syncthreads();
    if (is_last && tid == 0) {
        double pd = 0.0;
        #pragma unroll
        for (int bb = 0; bb < MAXB; bb++) {
            if (bb < B) {
                double Sb = *((volatile double*)&g_S[bb]);
                pd += Sb * Sb;
            }
        }
        pd -= *((volatile double*)&g_lin);
        double bn = *((volatile double*)&g_bn);
        double bd = *((volatile double*)&g_bd);
        double cl = *((volatile double*)&g_clash);
        double bond  = bn / (bd + 1e-8);
        double clash = 2.0 * cl / (pd + 1e-8);
        out[0] = (float)bond;
        out[1] = (float)clash;
        out[2] = (float)(bond + clash);
        // reset for next graph replay
        g_clash = 0.0; g_bn = 0.0; g_bd = 0.0; g_lin = 0.0; g_count = 0u;
        #pragma unroll
        for (int bb = 0; bb < MAXB; bb++) g_S[bb] = 0.0;
    }
}

extern "C" void kernel_launch(void* const* d_in, const int* in_sizes, int n_in,
                              void* d_out, int out_size)
{
    const float* pos  = (const float*)d_in[0];
    const float* mask = (const float*)d_in[1];
    int B = in_sizes[1] / L_FIXED;
    if (B > MAXB) B = MAXB;

    dim3 grid(NTP, B);
    fused_violation_kernel<<<grid, NTHREADS>>>(pos, mask, (float*)d_out, B);
}